// round 1
// baseline (speedup 1.0000x reference)
#include <cuda_runtime.h>

// Problem constants
#define NB     512     // batch per side
#define DIN    128
#define DH     256
#define DOUT   10
#define CCH    0       // differentiated output channel

// Feature row layout: [h1 (256) | d2 (256) | x (128) | d1 (256) | h2 (256)]
#define OFF_H1 0
#define OFF_D2 256
#define OFF_X  512
#define OFF_D1 640
#define OFF_H2 896
#define FDIM   1152

// Scratch (no allocation allowed in kernel_launch)
__device__ __align__(16) float g_feat[2 * NB * FDIM];   // 4.7 MB
__device__ float g_inv[2 * NB];

// ---------------------------------------------------------------------------
// Kernel 1: per-sample features + inverse Jacobian norm.
// One block (256 threads) per sample; 1024 blocks.
// ---------------------------------------------------------------------------
__device__ __forceinline__ float block_sum(float v, float* red, int tid) {
    red[tid] = v;
    __syncthreads();
#pragma unroll
    for (int s = 128; s > 0; s >>= 1) {
        if (tid < s) red[tid] += red[tid + s];
        __syncthreads();
    }
    float r = red[0];
    __syncthreads();
    return r;
}

__global__ __launch_bounds__(256) void feat_kernel(
    const float* __restrict__ x1, const float* __restrict__ x2,
    const float* __restrict__ W1, const float* __restrict__ b1,
    const float* __restrict__ W2, const float* __restrict__ b2,
    const float* __restrict__ W3)
{
    __shared__ __align__(16) float xs[DIN];
    __shared__ __align__(16) float h1s[DH];
    __shared__ __align__(16) float d2s[DH];
    __shared__ float red[256];

    const int tid = threadIdx.x;
    const int s   = blockIdx.x;
    const float* xp = (s < NB) ? (x1 + (size_t)s * DIN)
                               : (x2 + (size_t)(s - NB) * DIN);

    if (tid < DIN) xs[tid] = xp[tid];
    __syncthreads();

    // z1[j] = b1[j] + sum_i x[i] * W1[i][j]   (coalesced over j)
    float z1 = b1[tid];
#pragma unroll 8
    for (int i = 0; i < DIN; i++) z1 = fmaf(xs[i], W1[i * DH + tid], z1);
    const float h1 = fmaxf(z1, 0.f);
    h1s[tid] = h1;
    __syncthreads();

    // z2[j] = b2[j] + sum_i h1[i] * W2[i][j]
    float z2 = b2[tid];
#pragma unroll 8
    for (int i = 0; i < DH; i++) z2 = fmaf(h1s[i], W2[i * DH + tid], z2);
    const float h2 = fmaxf(z2, 0.f);
    const float d2 = (z2 > 0.f) ? W3[tid * DOUT + CCH] : 0.f;
    d2s[tid] = d2;
    __syncthreads();

    // d1[i] = relu'(z1[i]) * sum_j W2[i][j] * d2[j]   (row read, L2-hot)
    float d1 = 0.f;
    if (h1 > 0.f) {
        const float4* wrow = (const float4*)(W2 + (size_t)tid * DH);
        const float4* dv   = (const float4*)d2s;
        float acc = 0.f;
#pragma unroll 8
        for (int i = 0; i < DH / 4; i++) {
            float4 w = wrow[i];
            float4 d = dv[i];
            acc = fmaf(w.x, d.x, acc);
            acc = fmaf(w.y, d.y, acc);
            acc = fmaf(w.z, d.z, acc);
            acc = fmaf(w.w, d.w, acc);
        }
        d1 = acc;
    }

    // Norms -> inv_norm
    const float xc  = (tid < DIN) ? xs[tid] : 0.f;
    const float sx  = block_sum(xc * xc, red, tid);
    const float sh1 = block_sum(h1 * h1, red, tid);
    const float sh2 = block_sum(h2 * h2, red, tid);
    const float sd2 = block_sum(d2 * d2, red, tid);
    const float sd1 = block_sum(d1 * d1, red, tid);

    if (tid == 0) {
        const float normsq = 1.f + sh2 + (1.f + sh1) * sd2 + (1.f + sx) * sd1;
        g_inv[s] = rsqrtf(normsq);
    }

    float* fr = g_feat + (size_t)s * FDIM;
    fr[OFF_H1 + tid] = h1;
    fr[OFF_D2 + tid] = d2;
    fr[OFF_D1 + tid] = d1;
    fr[OFF_H2 + tid] = h2;
    if (tid < DIN) fr[OFF_X + tid] = xs[tid];
}

// ---------------------------------------------------------------------------
// Kernel 2: fused 5-segment Gram + NTK combine + normalization.
// 32x32 output tile per block (16x16 threads, 2x2 per thread). Grid 16x16.
// ---------------------------------------------------------------------------
__global__ __launch_bounds__(256) void gram_kernel(float* __restrict__ out)
{
    __shared__ float As[32][33];
    __shared__ float Bs[32][33];

    const int tx  = threadIdx.x;
    const int ty  = threadIdx.y;
    const int tid = ty * 16 + tx;
    const int ty2 = ty * 2;
    const int tx2 = tx * 2;

    const int rowA = blockIdx.y * 32;        // sample rows 0..511   (x1 side)
    const int rowB = NB + blockIdx.x * 32;   // sample rows 512..1023 (x2 side)

    const int lr = tid >> 3;          // 0..31  tile row loaded by this thread
    const int lc = (tid & 7) * 4;     // 0,4,..,28 tile col (float4)

    // Segment dot-product accumulator over [off, off+len)
    auto seg = [&](int off, int len, float a[2][2]) {
        a[0][0] = a[0][1] = a[1][0] = a[1][1] = 0.f;
        for (int kk = 0; kk < len; kk += 32) {
            const float4 va = *(const float4*)(g_feat + (size_t)(rowA + lr) * FDIM + off + kk + lc);
            const float4 vb = *(const float4*)(g_feat + (size_t)(rowB + lr) * FDIM + off + kk + lc);
            As[lr][lc + 0] = va.x; As[lr][lc + 1] = va.y;
            As[lr][lc + 2] = va.z; As[lr][lc + 3] = va.w;
            Bs[lr][lc + 0] = vb.x; Bs[lr][lc + 1] = vb.y;
            Bs[lr][lc + 2] = vb.z; Bs[lr][lc + 3] = vb.w;
            __syncthreads();
#pragma unroll
            for (int k = 0; k < 32; k++) {
                const float a0 = As[ty2 + 0][k];
                const float a1 = As[ty2 + 1][k];
                const float b0 = Bs[tx2 + 0][k];
                const float b1 = Bs[tx2 + 1][k];
                a[0][0] = fmaf(a0, b0, a[0][0]);
                a[0][1] = fmaf(a0, b1, a[0][1]);
                a[1][0] = fmaf(a1, b0, a[1][0]);
                a[1][1] = fmaf(a1, b1, a[1][1]);
            }
            __syncthreads();
        }
    };

    float res[2][2];
    float p[2][2], q[2][2];

    // (1 + G_h1) * G_d2
    seg(OFF_H1, DH, p);
    seg(OFF_D2, DH, q);
#pragma unroll
    for (int i = 0; i < 2; i++)
#pragma unroll
        for (int j = 0; j < 2; j++)
            res[i][j] = (1.f + p[i][j]) * q[i][j];

    // + (1 + G_x) * G_d1
    seg(OFF_X, DIN, p);
    seg(OFF_D1, DH, q);
#pragma unroll
    for (int i = 0; i < 2; i++)
#pragma unroll
        for (int j = 0; j < 2; j++)
            res[i][j] = fmaf(1.f + p[i][j], q[i][j], res[i][j]);

    // + 1 (b3 term) + G_h2 (W3 term)
    seg(OFF_H2, DH, p);
#pragma unroll
    for (int i = 0; i < 2; i++)
#pragma unroll
        for (int j = 0; j < 2; j++)
            res[i][j] += 1.f + p[i][j];

    // Normalize rows/cols and store
    const float ia0 = g_inv[rowA + ty2 + 0];
    const float ia1 = g_inv[rowA + ty2 + 1];
    const float ib0 = g_inv[rowB + tx2 + 0];
    const float ib1 = g_inv[rowB + tx2 + 1];
    const int outCol = blockIdx.x * 32 + tx2;

    out[(size_t)(rowA + ty2 + 0) * NB + outCol + 0] = res[0][0] * ia0 * ib0;
    out[(size_t)(rowA + ty2 + 0) * NB + outCol + 1] = res[0][1] * ia0 * ib1;
    out[(size_t)(rowA + ty2 + 1) * NB + outCol + 0] = res[1][0] * ia1 * ib0;
    out[(size_t)(rowA + ty2 + 1) * NB + outCol + 1] = res[1][1] * ia1 * ib1;
}

// ---------------------------------------------------------------------------
// Launch
// inputs (metadata order): x1, x2, W1, b1, W2, b2, W3, b3
// output: [512, 512] float32
// ---------------------------------------------------------------------------
extern "C" void kernel_launch(void* const* d_in, const int* in_sizes, int n_in,
                              void* d_out, int out_size)
{
    const float* x1 = (const float*)d_in[0];
    const float* x2 = (const float*)d_in[1];
    const float* W1 = (const float*)d_in[2];
    const float* b1 = (const float*)d_in[3];
    const float* W2 = (const float*)d_in[4];
    const float* b2 = (const float*)d_in[5];
    const float* W3 = (const float*)d_in[6];
    float* out = (float*)d_out;

    feat_kernel<<<2 * NB, 256>>>(x1, x2, W1, b1, W2, b2, W3);
    gram_kernel<<<dim3(16, 16), dim3(16, 16)>>>(out);
}

// round 2
// speedup vs baseline: 2.4271x; 2.4271x over previous
#include <cuda_runtime.h>

// Problem constants
#define NB     512
#define DIN    128
#define DH     256
#define DOUT   10
#define CCH    0

// Feature layout per sample: [h1(256) | d2(256) | x(128) | d1(256) | h2(256)]
#define OFF_H1 0
#define OFF_D2 256
#define OFF_X  512
#define OFF_D1 640
#define OFF_H2 896
#define FDIM   1152

#define GRP    8      // samples per feat block
#define KB     16     // gram k sub-chunk (double buffered)
#define RPAD   132    // padded smem row (floats), 16B-aligned rows

// Scratch
__device__ __align__(16) float g_feat[2 * NB * FDIM];            // 4.7 MB
__device__ float g_inv[2 * NB];
__device__ __align__(16) float g_scr[9 * NB * NB];               // 9.4 MB chunk grams

// ---------------------------------------------------------------------------
// Kernel 1: features for 8 samples per block. 128 blocks x 256 threads.
// Thread tid owns column j = tid (z1/z2/d2) and row i = tid (d1) for all 8
// samples; W1/W2 are read ONCE per block and amortized across the 8 samples.
// ---------------------------------------------------------------------------
__global__ __launch_bounds__(256) void feat_kernel(
    const float* __restrict__ x1, const float* __restrict__ x2,
    const float* __restrict__ W1, const float* __restrict__ b1,
    const float* __restrict__ W2, const float* __restrict__ b2,
    const float* __restrict__ W3)
{
    __shared__ __align__(16) float xs [GRP][DIN];
    __shared__ __align__(16) float h1s[GRP][DH];
    __shared__ __align__(16) float d2s[GRP][DH];
    __shared__ float wred[5][8][GRP];     // [quantity][warp][sample]
    __shared__ float sred[5][GRP];

    const int tid  = threadIdx.x;
    const int lane = tid & 31;
    const int warp = tid >> 5;
    const int q0   = blockIdx.x * GRP;

    // Load x for 8 samples (one float4 per thread)
    {
        const int s = tid >> 5, f = tid & 31;
        const int q = q0 + s;
        const float* xp = (q < NB) ? (x1 + (size_t)q * DIN)
                                   : (x2 + (size_t)(q - NB) * DIN);
        ((float4*)xs[s])[f] = ((const float4*)xp)[f];
    }
    __syncthreads();

    const int j = tid;

    // ---- z1 / h1 ----
    float h1v[GRP];
    {
        float acc[GRP];
        const float bj = b1[j];
#pragma unroll
        for (int s = 0; s < GRP; s++) acc[s] = bj;
#pragma unroll 4
        for (int i4 = 0; i4 < DIN / 4; i4++) {
            const float w0 = W1[(i4 * 4 + 0) * DH + j];
            const float w1 = W1[(i4 * 4 + 1) * DH + j];
            const float w2 = W1[(i4 * 4 + 2) * DH + j];
            const float w3 = W1[(i4 * 4 + 3) * DH + j];
#pragma unroll
            for (int s = 0; s < GRP; s++) {
                const float4 xv = ((const float4*)xs[s])[i4];
                acc[s] = fmaf(xv.x, w0, acc[s]);
                acc[s] = fmaf(xv.y, w1, acc[s]);
                acc[s] = fmaf(xv.z, w2, acc[s]);
                acc[s] = fmaf(xv.w, w3, acc[s]);
            }
        }
#pragma unroll
        for (int s = 0; s < GRP; s++) {
            h1v[s] = fmaxf(acc[s], 0.f);
            h1s[s][j] = h1v[s];
        }
    }
    __syncthreads();

    // ---- z2 / h2 / d2 ----
    float h2v[GRP], d2v[GRP];
    {
        float acc[GRP];
        const float bj = b2[j];
#pragma unroll
        for (int s = 0; s < GRP; s++) acc[s] = bj;
#pragma unroll 4
        for (int i4 = 0; i4 < DH / 4; i4++) {
            const float w0 = W2[(i4 * 4 + 0) * DH + j];
            const float w1 = W2[(i4 * 4 + 1) * DH + j];
            const float w2 = W2[(i4 * 4 + 2) * DH + j];
            const float w3 = W2[(i4 * 4 + 3) * DH + j];
#pragma unroll
            for (int s = 0; s < GRP; s++) {
                const float4 h = ((const float4*)h1s[s])[i4];
                acc[s] = fmaf(h.x, w0, acc[s]);
                acc[s] = fmaf(h.y, w1, acc[s]);
                acc[s] = fmaf(h.z, w2, acc[s]);
                acc[s] = fmaf(h.w, w3, acc[s]);
            }
        }
        const float w3c = W3[j * DOUT + CCH];
#pragma unroll
        for (int s = 0; s < GRP; s++) {
            h2v[s] = fmaxf(acc[s], 0.f);
            d2v[s] = (acc[s] > 0.f) ? w3c : 0.f;
            d2s[s][j] = d2v[s];
        }
    }
    __syncthreads();

    // ---- d1 (row i = tid of W2) ----
    float d1v[GRP];
    {
        float acc[GRP];
#pragma unroll
        for (int s = 0; s < GRP; s++) acc[s] = 0.f;
        const float4* wrow = (const float4*)(W2 + (size_t)tid * DH);
#pragma unroll 4
        for (int jf = 0; jf < DH / 4; jf++) {
            const float4 w = wrow[jf];
#pragma unroll
            for (int s = 0; s < GRP; s++) {
                const float4 d = ((const float4*)d2s[s])[jf];
                acc[s] = fmaf(w.x, d.x, acc[s]);
                acc[s] = fmaf(w.y, d.y, acc[s]);
                acc[s] = fmaf(w.z, d.z, acc[s]);
                acc[s] = fmaf(w.w, d.w, acc[s]);
            }
        }
#pragma unroll
        for (int s = 0; s < GRP; s++)
            d1v[s] = (h1v[s] > 0.f) ? acc[s] : 0.f;
    }

    // ---- norms: 5 quantities x 8 samples, warp shuffle then smem ----
    {
        float v[5][GRP];
#pragma unroll
        for (int s = 0; s < GRP; s++) {
            const float xv = (tid < DIN) ? xs[s][tid] : 0.f;
            v[0][s] = xv * xv;
            v[1][s] = h1v[s] * h1v[s];
            v[2][s] = d2v[s] * d2v[s];
            v[3][s] = d1v[s] * d1v[s];
            v[4][s] = h2v[s] * h2v[s];
        }
#pragma unroll
        for (int q = 0; q < 5; q++) {
#pragma unroll
            for (int s = 0; s < GRP; s++) {
#pragma unroll
                for (int o = 16; o > 0; o >>= 1)
                    v[q][s] += __shfl_xor_sync(0xffffffffu, v[q][s], o);
            }
            if (lane == 0) {
#pragma unroll
                for (int s = 0; s < GRP; s++) wred[q][warp][s] = v[q][s];
            }
        }
        __syncthreads();
        if (tid < 40) {
            const int q = tid >> 3, s = tid & 7;
            float t = 0.f;
#pragma unroll
            for (int w = 0; w < 8; w++) t += wred[q][w][s];
            sred[q][s] = t;
        }
        __syncthreads();
        if (tid < GRP) {
            const int s = tid;
            const float normsq = 1.f + sred[4][s]
                               + (1.f + sred[1][s]) * sred[2][s]
                               + (1.f + sred[0][s]) * sred[3][s];
            g_inv[q0 + s] = rsqrtf(normsq);
        }
    }

    // ---- store features ----
#pragma unroll
    for (int s = 0; s < GRP; s++) {
        float* fr = g_feat + (size_t)(q0 + s) * FDIM;
        fr[OFF_H1 + j] = h1v[s];
        fr[OFF_D2 + j] = d2v[s];
        fr[OFF_D1 + j] = d1v[s];
        fr[OFF_H2 + j] = h2v[s];
        if (tid < DIN) fr[OFF_X + tid] = xs[s][tid];
    }
}

// ---------------------------------------------------------------------------
// Kernel 2: split-K chunk grams. Grid (16 tiles, 9 chunks) = 144 blocks.
// Tile = 128x128 output, K = 128 per chunk, 256 threads, 8x8 per thread.
// Smem is k-major [k][m] (RPAD=132 row), fragments split (4 + 4 at +64)
// for conflict-free LDS.128.
// ---------------------------------------------------------------------------
__global__ __launch_bounds__(256) void gram_kernel()
{
    __shared__ __align__(16) float As[2][KB][RPAD];
    __shared__ __align__(16) float Bs[2][KB][RPAD];

    const int tid   = threadIdx.x;
    const int tx    = tid & 15;          // 0..15 -> cols
    const int ty    = tid >> 4;          // 0..15 -> rows
    const int tile  = blockIdx.x;        // 0..15
    const int chunk = blockIdx.y;        // 0..8
    const int ti    = tile >> 2;
    const int tj    = tile & 3;

    const int arow0 = ti * 128;          // x1-side samples
    const int brow0 = NB + tj * 128;     // x2-side samples
    const int kbase = chunk * 128;

    // Loader mapping: element e in [0,512): row = e>>2, f4 = e&3
    const int e0r = tid >> 2,        e0f = tid & 3;
    const int e1r = (tid + 256) >> 2, e1f = (tid + 256) & 3;

    float4 pa0, pa1, pb0, pb1;

    auto load_stage = [&](int st) {
        const int kk = kbase + st * KB;
        pa0 = *(const float4*)(g_feat + (size_t)(arow0 + e0r) * FDIM + kk + e0f * 4);
        pa1 = *(const float4*)(g_feat + (size_t)(arow0 + e1r) * FDIM + kk + e1f * 4);
        pb0 = *(const float4*)(g_feat + (size_t)(brow0 + e0r) * FDIM + kk + e0f * 4);
        pb1 = *(const float4*)(g_feat + (size_t)(brow0 + e1r) * FDIM + kk + e1f * 4);
    };
    auto store_stage = [&](int b) {
        As[b][e0f * 4 + 0][e0r] = pa0.x; As[b][e0f * 4 + 1][e0r] = pa0.y;
        As[b][e0f * 4 + 2][e0r] = pa0.z; As[b][e0f * 4 + 3][e0r] = pa0.w;
        As[b][e1f * 4 + 0][e1r] = pa1.x; As[b][e1f * 4 + 1][e1r] = pa1.y;
        As[b][e1f * 4 + 2][e1r] = pa1.z; As[b][e1f * 4 + 3][e1r] = pa1.w;
        Bs[b][e0f * 4 + 0][e0r] = pb0.x; Bs[b][e0f * 4 + 1][e0r] = pb0.y;
        Bs[b][e0f * 4 + 2][e0r] = pb0.z; Bs[b][e0f * 4 + 3][e0r] = pb0.w;
        Bs[b][e1f * 4 + 0][e1r] = pb1.x; Bs[b][e1f * 4 + 1][e1r] = pb1.y;
        Bs[b][e1f * 4 + 2][e1r] = pb1.z; Bs[b][e1f * 4 + 3][e1r] = pb1.w;
    };

    float acc[8][8];
#pragma unroll
    for (int i = 0; i < 8; i++)
#pragma unroll
        for (int jj = 0; jj < 8; jj++) acc[i][jj] = 0.f;

    load_stage(0);
    store_stage(0);
    __syncthreads();

    const int NSTAGE = 128 / KB;   // 8
#pragma unroll 1
    for (int st = 0; st < NSTAGE; st++) {
        if (st < NSTAGE - 1) load_stage(st + 1);
        const int b = st & 1;
#pragma unroll
        for (int k = 0; k < KB; k++) {
            const float4 a0 = *(const float4*)&As[b][k][ty * 4];
            const float4 a1 = *(const float4*)&As[b][k][64 + ty * 4];
            const float4 b0 = *(const float4*)&Bs[b][k][tx * 4];
            const float4 b1 = *(const float4*)&Bs[b][k][64 + tx * 4];
            const float av[8] = {a0.x, a0.y, a0.z, a0.w, a1.x, a1.y, a1.z, a1.w};
            const float bv[8] = {b0.x, b0.y, b0.z, b0.w, b1.x, b1.y, b1.z, b1.w};
#pragma unroll
            for (int i = 0; i < 8; i++)
#pragma unroll
                for (int jj = 0; jj < 8; jj++)
                    acc[i][jj] = fmaf(av[i], bv[jj], acc[i][jj]);
        }
        if (st < NSTAGE - 1) store_stage(b ^ 1);
        __syncthreads();
    }

    // Epilogue: write 128x128 chunk gram to scratch
    float* scr = g_scr + (size_t)chunk * NB * NB;
#pragma unroll
    for (int ri = 0; ri < 2; ri++) {
#pragma unroll
        for (int r = 0; r < 4; r++) {
            const int m = ti * 128 + ri * 64 + ty * 4 + r;
            float* rp = scr + (size_t)m * NB + tj * 128;
            float4 v0, v1;
            v0.x = acc[ri * 4 + r][0]; v0.y = acc[ri * 4 + r][1];
            v0.z = acc[ri * 4 + r][2]; v0.w = acc[ri * 4 + r][3];
            v1.x = acc[ri * 4 + r][4]; v1.y = acc[ri * 4 + r][5];
            v1.z = acc[ri * 4 + r][6]; v1.w = acc[ri * 4 + r][7];
            *(float4*)(rp + tx * 4)      = v0;
            *(float4*)(rp + 64 + tx * 4) = v1;
        }
    }
}

// ---------------------------------------------------------------------------
// Kernel 3: combine chunk grams + normalize. 256 blocks x 256 threads,
// one float4 of out per thread.
// chunks: 0,1 -> h1 | 2,3 -> d2 | 4 -> x | 5,6 -> d1 | 7,8 -> h2
// ---------------------------------------------------------------------------
__global__ __launch_bounds__(256) void combine_kernel(float* __restrict__ out)
{
    const int gid = blockIdx.x * 256 + threadIdx.x;   // 0..65535
    const int row = gid >> 7;
    const int c4  = gid & 127;

    const size_t off = (size_t)row * NB;
    float4 g[9];
#pragma unroll
    for (int c = 0; c < 9; c++)
        g[c] = ((const float4*)(g_scr + (size_t)c * NB * NB + off))[c4];

    const float  ia = g_inv[row];
    const float4 ib = *(const float4*)&g_inv[NB + c4 * 4];

    float4 r;
    r.x = (1.f + g[7].x + g[8].x + (1.f + g[0].x + g[1].x) * (g[2].x + g[3].x)
           + (1.f + g[4].x) * (g[5].x + g[6].x)) * ia * ib.x;
    r.y = (1.f + g[7].y + g[8].y + (1.f + g[0].y + g[1].y) * (g[2].y + g[3].y)
           + (1.f + g[4].y) * (g[5].y + g[6].y)) * ia * ib.y;
    r.z = (1.f + g[7].z + g[8].z + (1.f + g[0].z + g[1].z) * (g[2].z + g[3].z)
           + (1.f + g[4].z) * (g[5].z + g[6].z)) * ia * ib.z;
    r.w = (1.f + g[7].w + g[8].w + (1.f + g[0].w + g[1].w) * (g[2].w + g[3].w)
           + (1.f + g[4].w) * (g[5].w + g[6].w)) * ia * ib.w;

    ((float4*)(out + off))[c4] = r;
}

// ---------------------------------------------------------------------------
// inputs: x1, x2, W1, b1, W2, b2, W3, b3 ; output [512,512] float32
// ---------------------------------------------------------------------------
extern "C" void kernel_launch(void* const* d_in, const int* in_sizes, int n_in,
                              void* d_out, int out_size)
{
    const float* x1 = (const float*)d_in[0];
    const float* x2 = (const float*)d_in[1];
    const float* W1 = (const float*)d_in[2];
    const float* b1 = (const float*)d_in[3];
    const float* W2 = (const float*)d_in[4];
    const float* b2 = (const float*)d_in[5];
    const float* W3 = (const float*)d_in[6];
    float* out = (float*)d_out;

    feat_kernel<<<(2 * NB) / GRP, 256>>>(x1, x2, W1, b1, W2, b2, W3);
    gram_kernel<<<dim3(16, 9), 256>>>();
    combine_kernel<<<256, 256>>>(out);
}

// round 4
// speedup vs baseline: 2.6235x; 1.0809x over previous
#include <cuda_runtime.h>

// Problem constants
#define NB     512
#define DIN    128
#define DH     256
#define DOUT   10
#define CCH    0

// Feature layout per sample: [h1(256) | d2(256) | x(128) | d1(256) | h2(256)]
#define OFF_H1 0
#define OFF_D2 256
#define OFF_X  512
#define OFF_D1 640
#define OFF_H2 896
#define FDIM   1152

#define GRP    8      // samples per feat block
#define KB     16     // gram k sub-chunk (double buffered)
#define RPAD   132    // padded smem row (floats)

// norm indices
#define NX  0
#define NH1 1
#define ND2 2
#define ND1 3
#define NH2 4

// Scratch
__device__ __align__(16) float g_feat[2 * NB * FDIM];   // 4.7 MB
__device__ float g_inv[2 * NB];
__device__ __align__(16) float g_scr[9 * NB * NB];      // 9.4 MB chunk grams
__device__ __align__(16) float g_w2t[DH * DH];          // W2 transposed

// ---------------------------------------------------------------------------
// Kernel 0: W2 transpose (g_w2t[j][i] = W2[i][j]). 64 blocks x 256 threads.
// ---------------------------------------------------------------------------
__global__ __launch_bounds__(256) void w2t_kernel(const float* __restrict__ W2)
{
    __shared__ float t[32][33];
    const int tx = threadIdx.x & 31;
    const int ty = threadIdx.x >> 5;          // 0..7
    const int x0 = blockIdx.x * 32;
    const int y0 = blockIdx.y * 32;
#pragma unroll
    for (int r = 0; r < 4; r++)
        t[ty + 8 * r][tx] = W2[(size_t)(y0 + ty + 8 * r) * DH + x0 + tx];
    __syncthreads();
#pragma unroll
    for (int r = 0; r < 4; r++)
        g_w2t[(size_t)(x0 + ty + 8 * r) * DH + y0 + tx] = t[tx][ty + 8 * r];
}

// ---------------------------------------------------------------------------
// Kernel 1: features, 8 samples/block, 1024 threads, 4-way K-split.
// 128 blocks. Threads: col j = tid&255, K-quarter kq = tid>>8.
// ---------------------------------------------------------------------------
__global__ __launch_bounds__(1024, 1) void feat_kernel(
    const float* __restrict__ x1, const float* __restrict__ x2,
    const float* __restrict__ W1, const float* __restrict__ b1,
    const float* __restrict__ W2, const float* __restrict__ b2,
    const float* __restrict__ W3)
{
    __shared__ __align__(16) float xs [GRP][DIN];     // 4 KB
    __shared__ __align__(16) float h1s[GRP][DH];      // 8 KB
    __shared__ __align__(16) float d2s[GRP][DH];      // 8 KB
    __shared__ __align__(16) float part[3][GRP][DH];  // 24 KB
    __shared__ float nacc[GRP][8];

    const int tid  = threadIdx.x;
    const int lane = tid & 31;
    const int q0   = blockIdx.x * GRP;
    const int j    = tid & 255;
    const int kq   = tid >> 8;

    if (tid < GRP * 8) nacc[tid >> 3][tid & 7] = 0.f;
    __syncthreads();

    // ---- load x + x^2 norm + store x to g_feat ----
    {
        const int s = tid >> 7;            // warp-uniform
        const int i = tid & 127;
        const int q = q0 + s;
        const float* xp = (q < NB) ? (x1 + (size_t)q * DIN)
                                   : (x2 + (size_t)(q - NB) * DIN);
        const float v = xp[i];
        xs[s][i] = v;
        g_feat[(size_t)q * FDIM + OFF_X + i] = v;
        float ss = v * v;
#pragma unroll
        for (int o = 16; o > 0; o >>= 1) ss += __shfl_xor_sync(~0u, ss, o);
        if (lane == 0) atomicAdd(&nacc[s][NX], ss);
    }
    __syncthreads();

    // ================= z1 / h1 =================
    {
        float acc[GRP];
#pragma unroll
        for (int s = 0; s < GRP; s++) acc[s] = 0.f;
        const int i0 = kq * (DIN / 4);               // 32 rows per quarter
#pragma unroll
        for (int i4 = 0; i4 < DIN / 16; i4++) {      // 8 float4 steps
            const int ib = i0 + i4 * 4;
            const float w0 = W1[(ib + 0) * DH + j];
            const float w1 = W1[(ib + 1) * DH + j];
            const float w2v = W1[(ib + 2) * DH + j];
            const float w3v = W1[(ib + 3) * DH + j];
#pragma unroll
            for (int s = 0; s < GRP; s++) {
                const float4 xv = ((const float4*)xs[s])[ib >> 2];
                acc[s] = fmaf(xv.x, w0,  acc[s]);
                acc[s] = fmaf(xv.y, w1,  acc[s]);
                acc[s] = fmaf(xv.z, w2v, acc[s]);
                acc[s] = fmaf(xv.w, w3v, acc[s]);
            }
        }
        if (kq > 0) {
#pragma unroll
            for (int s = 0; s < GRP; s++) part[kq - 1][s][j] = acc[s];
        }
        __syncthreads();
        if (kq == 0) {
            const float bj = b1[j];
            float v[GRP];
#pragma unroll
            for (int s = 0; s < GRP; s++) {
                const float z = acc[s] + part[0][s][j] + part[1][s][j]
                              + part[2][s][j] + bj;
                const float h1 = fmaxf(z, 0.f);
                h1s[s][j] = h1;
                g_feat[(size_t)(q0 + s) * FDIM + OFF_H1 + j] = h1;
                v[s] = h1 * h1;
            }
#pragma unroll
            for (int s = 0; s < GRP; s++) {
#pragma unroll
                for (int o = 16; o > 0; o >>= 1)
                    v[s] += __shfl_xor_sync(~0u, v[s], o);
            }
            if (lane == 0) {
#pragma unroll
                for (int s = 0; s < GRP; s++) atomicAdd(&nacc[s][NH1], v[s]);
            }
        }
        __syncthreads();
    }

    // ================= z2 / h2 / d2 =================
    {
        float acc[GRP];
#pragma unroll
        for (int s = 0; s < GRP; s++) acc[s] = 0.f;
        const int i0 = kq * (DH / 4);                // 64 rows per quarter
#pragma unroll
        for (int i4 = 0; i4 < DH / 16; i4++) {       // 16 float4 steps
            const int ib = i0 + i4 * 4;
            const float w0 = W2[(ib + 0) * DH + j];
            const float w1 = W2[(ib + 1) * DH + j];
            const float w2v = W2[(ib + 2) * DH + j];
            const float w3v = W2[(ib + 3) * DH + j];
#pragma unroll
            for (int s = 0; s < GRP; s++) {
                const float4 h = ((const float4*)h1s[s])[ib >> 2];
                acc[s] = fmaf(h.x, w0,  acc[s]);
                acc[s] = fmaf(h.y, w1,  acc[s]);
                acc[s] = fmaf(h.z, w2v, acc[s]);
                acc[s] = fmaf(h.w, w3v, acc[s]);
            }
        }
        if (kq > 0) {
#pragma unroll
            for (int s = 0; s < GRP; s++) part[kq - 1][s][j] = acc[s];
        }
        __syncthreads();
        if (kq == 0) {
            const float bj  = b2[j];
            const float w3c = W3[j * DOUT + CCH];
            float vh[GRP], vd[GRP];
#pragma unroll
            for (int s = 0; s < GRP; s++) {
                const float z = acc[s] + part[0][s][j] + part[1][s][j]
                              + part[2][s][j] + bj;
                const float h2 = fmaxf(z, 0.f);
                const float d2 = (z > 0.f) ? w3c : 0.f;
                d2s[s][j] = d2;
                float* fr = g_feat + (size_t)(q0 + s) * FDIM;
                fr[OFF_H2 + j] = h2;
                fr[OFF_D2 + j] = d2;
                vh[s] = h2 * h2;
                vd[s] = d2 * d2;
            }
#pragma unroll
            for (int s = 0; s < GRP; s++) {
#pragma unroll
                for (int o = 16; o > 0; o >>= 1) {
                    vh[s] += __shfl_xor_sync(~0u, vh[s], o);
                    vd[s] += __shfl_xor_sync(~0u, vd[s], o);
                }
            }
            if (lane == 0) {
#pragma unroll
                for (int s = 0; s < GRP; s++) {
                    atomicAdd(&nacc[s][NH2], vh[s]);
                    atomicAdd(&nacc[s][ND2], vd[s]);
                }
            }
        }
        __syncthreads();
    }

    // ================= d1 (uses W2T, coalesced) =================
    {
        float acc[GRP];
#pragma unroll
        for (int s = 0; s < GRP; s++) acc[s] = 0.f;
        const int i  = j;                            // output row
        const int j0 = kq * (DH / 4);                // 64 cols per quarter
#pragma unroll
        for (int j4 = 0; j4 < DH / 16; j4++) {       // 16 float4 steps
            const int jb = j0 + j4 * 4;
            const float w0 = g_w2t[(jb + 0) * DH + i];
            const float w1 = g_w2t[(jb + 1) * DH + i];
            const float w2v = g_w2t[(jb + 2) * DH + i];
            const float w3v = g_w2t[(jb + 3) * DH + i];
#pragma unroll
            for (int s = 0; s < GRP; s++) {
                const float4 d = ((const float4*)d2s[s])[jb >> 2];
                acc[s] = fmaf(d.x, w0,  acc[s]);
                acc[s] = fmaf(d.y, w1,  acc[s]);
                acc[s] = fmaf(d.z, w2v, acc[s]);
                acc[s] = fmaf(d.w, w3v, acc[s]);
            }
        }
        if (kq > 0) {
#pragma unroll
            for (int s = 0; s < GRP; s++) part[kq - 1][s][i] = acc[s];
        }
        __syncthreads();
        if (kq == 0) {
            float v[GRP];
#pragma unroll
            for (int s = 0; s < GRP; s++) {
                const float t = acc[s] + part[0][s][i] + part[1][s][i]
                              + part[2][s][i];
                const float d1 = (h1s[s][i] > 0.f) ? t : 0.f;
                g_feat[(size_t)(q0 + s) * FDIM + OFF_D1 + i] = d1;
                v[s] = d1 * d1;
            }
#pragma unroll
            for (int s = 0; s < GRP; s++) {
#pragma unroll
                for (int o = 16; o > 0; o >>= 1)
                    v[s] += __shfl_xor_sync(~0u, v[s], o);
            }
            if (lane == 0) {
#pragma unroll
                for (int s = 0; s < GRP; s++) atomicAdd(&nacc[s][ND1], v[s]);
            }
        }
        __syncthreads();
    }

    // ---- inverse norms ----
    if (tid < GRP) {
        const int s = tid;
        const float normsq = 1.f + nacc[s][NH2]
                           + (1.f + nacc[s][NH1]) * nacc[s][ND2]
                           + (1.f + nacc[s][NX])  * nacc[s][ND1];
        g_inv[q0 + s] = rsqrtf(normsq);
    }
}

// ---------------------------------------------------------------------------
// Kernel 2: split-K chunk grams. Grid (16 tiles, 9 chunks) = 144 blocks,
// 256 threads, 8x8 per thread, k-major smem, double buffered.
// ---------------------------------------------------------------------------
__global__ __launch_bounds__(256) void gram_kernel()
{
    __shared__ __align__(16) float As[2][KB][RPAD];
    __shared__ __align__(16) float Bs[2][KB][RPAD];

    const int tid   = threadIdx.x;
    const int tx    = tid & 15;
    const int ty    = tid >> 4;
    const int tile  = blockIdx.x;
    const int chunk = blockIdx.y;
    const int ti    = tile >> 2;
    const int tj    = tile & 3;

    const int arow0 = ti * 128;
    const int brow0 = NB + tj * 128;
    const int kbase = chunk * 128;

    const int e0r = tid >> 2,         e0f = tid & 3;
    const int e1r = (tid + 256) >> 2, e1f = (tid + 256) & 3;

    float4 pa0, pa1, pb0, pb1;

    auto load_stage = [&](int st) {
        const int kk = kbase + st * KB;
        pa0 = *(const float4*)(g_feat + (size_t)(arow0 + e0r) * FDIM + kk + e0f * 4);
        pa1 = *(const float4*)(g_feat + (size_t)(arow0 + e1r) * FDIM + kk + e1f * 4);
        pb0 = *(const float4*)(g_feat + (size_t)(brow0 + e0r) * FDIM + kk + e0f * 4);
        pb1 = *(const float4*)(g_feat + (size_t)(brow0 + e1r) * FDIM + kk + e1f * 4);
    };
    auto store_stage = [&](int b) {
        As[b][e0f * 4 + 0][e0r] = pa0.x; As[b][e0f * 4 + 1][e0r] = pa0.y;
        As[b][e0f * 4 + 2][e0r] = pa0.z; As[b][e0f * 4 + 3][e0r] = pa0.w;
        As[b][e1f * 4 + 0][e1r] = pa1.x; As[b][e1f * 4 + 1][e1r] = pa1.y;
        As[b][e1f * 4 + 2][e1r] = pa1.z; As[b][e1f * 4 + 3][e1r] = pa1.w;
        Bs[b][e0f * 4 + 0][e0r] = pb0.x; Bs[b][e0f * 4 + 1][e0r] = pb0.y;
        Bs[b][e0f * 4 + 2][e0r] = pb0.z; Bs[b][e0f * 4 + 3][e0r] = pb0.w;
        Bs[b][e1f * 4 + 0][e1r] = pb1.x; Bs[b][e1f * 4 + 1][e1r] = pb1.y;
        Bs[b][e1f * 4 + 2][e1r] = pb1.z; Bs[b][e1f * 4 + 3][e1r] = pb1.w;
    };

    float acc[8][8];
#pragma unroll
    for (int i = 0; i < 8; i++)
#pragma unroll
        for (int jj = 0; jj < 8; jj++) acc[i][jj] = 0.f;

    load_stage(0);
    store_stage(0);
    __syncthreads();

    const int NSTAGE = 128 / KB;
#pragma unroll 1
    for (int st = 0; st < NSTAGE; st++) {
        if (st < NSTAGE - 1) load_stage(st + 1);
        const int b = st & 1;
#pragma unroll
        for (int k = 0; k < KB; k++) {
            const float4 a0 = *(const float4*)&As[b][k][ty * 4];
            const float4 a1 = *(const float4*)&As[b][k][64 + ty * 4];
            const float4 b0 = *(const float4*)&Bs[b][k][tx * 4];
            const float4 b1 = *(const float4*)&Bs[b][k][64 + tx * 4];
            const float av[8] = {a0.x, a0.y, a0.z, a0.w, a1.x, a1.y, a1.z, a1.w};
            const float bv[8] = {b0.x, b0.y, b0.z, b0.w, b1.x, b1.y, b1.z, b1.w};
#pragma unroll
            for (int i = 0; i < 8; i++)
#pragma unroll
                for (int jj = 0; jj < 8; jj++)
                    acc[i][jj] = fmaf(av[i], bv[jj], acc[i][jj]);
        }
        if (st < NSTAGE - 1) store_stage(b ^ 1);
        __syncthreads();
    }

    float* scr = g_scr + (size_t)chunk * NB * NB;
#pragma unroll
    for (int ri = 0; ri < 2; ri++) {
#pragma unroll
        for (int r = 0; r < 4; r++) {
            const int m = ti * 128 + ri * 64 + ty * 4 + r;
            float* rp = scr + (size_t)m * NB + tj * 128;
            float4 v0, v1;
            v0.x = acc[ri * 4 + r][0]; v0.y = acc[ri * 4 + r][1];
            v0.z = acc[ri * 4 + r][2]; v0.w = acc[ri * 4 + r][3];
            v1.x = acc[ri * 4 + r][4]; v1.y = acc[ri * 4 + r][5];
            v1.z = acc[ri * 4 + r][6]; v1.w = acc[ri * 4 + r][7];
            *(float4*)(rp + tx * 4)      = v0;
            *(float4*)(rp + 64 + tx * 4) = v1;
        }
    }
}

// ---------------------------------------------------------------------------
// Kernel 3: combine chunk grams + normalize.
// chunks: 0,1 -> h1 | 2,3 -> d2 | 4 -> x | 5,6 -> d1 | 7,8 -> h2
// ---------------------------------------------------------------------------
__global__ __launch_bounds__(256) void combine_kernel(float* __restrict__ out)
{
    const int gid = blockIdx.x * 256 + threadIdx.x;
    const int row = gid >> 7;
    const int c4  = gid & 127;

    const size_t off = (size_t)row * NB;
    float4 g[9];
#pragma unroll
    for (int c = 0; c < 9; c++)
        g[c] = ((const float4*)(g_scr + (size_t)c * NB * NB + off))[c4];

    const float  ia = g_inv[row];
    const float4 ib = *(const float4*)&g_inv[NB + c4 * 4];

    float4 r;
    r.x = (1.f + g[7].x + g[8].x + (1.f + g[0].x + g[1].x) * (g[2].x + g[3].x)
           + (1.f + g[4].x) * (g[5].x + g[6].x)) * ia * ib.x;
    r.y = (1.f + g[7].y + g[8].y + (1.f + g[0].y + g[1].y) * (g[2].y + g[3].y)
           + (1.f + g[4].y) * (g[5].y + g[6].y)) * ia * ib.y;
    r.z = (1.f + g[7].z + g[8].z + (1.f + g[0].z + g[1].z) * (g[2].z + g[3].z)
           + (1.f + g[4].z) * (g[5].z + g[6].z)) * ia * ib.z;
    r.w = (1.f + g[7].w + g[8].w + (1.f + g[0].w + g[1].w) * (g[2].w + g[3].w)
           + (1.f + g[4].w) * (g[5].w + g[6].w)) * ia * ib.w;

    ((float4*)(out + off))[c4] = r;
}

// ---------------------------------------------------------------------------
// inputs: x1, x2, W1, b1, W2, b2, W3, b3 ; output [512,512] float32
// ---------------------------------------------------------------------------
extern "C" void kernel_launch(void* const* d_in, const int* in_sizes, int n_in,
                              void* d_out, int out_size)
{
    const float* x1 = (const float*)d_in[0];
    const float* x2 = (const float*)d_in[1];
    const float* W1 = (const float*)d_in[2];
    const float* b1 = (const float*)d_in[3];
    const float* W2 = (const float*)d_in[4];
    const float* b2 = (const float*)d_in[5];
    const float* W3 = (const float*)d_in[6];
    float* out = (float*)d_out;

    w2t_kernel<<<dim3(8, 8), 256>>>(W2);
    feat_kernel<<<(2 * NB) / GRP, 1024>>>(x1, x2, W1, b1, W2, b2, W3);
    gram_kernel<<<dim3(16, 9), 256>>>();
    combine_kernel<<<256, 256>>>(out);
}

// round 5
// speedup vs baseline: 2.7738x; 1.0573x over previous
#include <cuda_runtime.h>

typedef unsigned long long u64;

// Problem constants
#define NB     512
#define DIN    128
#define DH     256
#define DOUT   10
#define CCH    0

// Feature layout per sample: [h1(256) | d2(256) | x(128) | d1(256) | h2(256)]
#define OFF_H1 0
#define OFF_D2 256
#define OFF_X  512
#define OFF_D1 640
#define OFF_H2 896
#define FDIM   1152

#define GRP    8      // samples per feat block
#define KB     16     // gram k sub-chunk (double buffered)
#define RPAD   132    // padded smem row (floats)

// norm indices
#define NX  0
#define NH1 1
#define ND2 2
#define ND1 3
#define NH2 4

// Scratch
__device__ __align__(16) float g_feat[2 * NB * FDIM];   // 4.7 MB
__device__ float g_inv[2 * NB];
__device__ __align__(16) float g_scr[9 * NB * NB];      // 9.4 MB chunk grams
__device__ __align__(16) float g_w2t[DH * DH];          // W2 transposed

// ---- packed f32x2 helpers (Blackwell) ----
__device__ __forceinline__ u64 pack2(float lo, float hi) {
    u64 r; asm("mov.b64 %0, {%1, %2};" : "=l"(r) : "f"(lo), "f"(hi)); return r;
}
__device__ __forceinline__ float2 unpk2(u64 v) {
    float2 r; asm("mov.b64 {%0, %1}, %2;" : "=f"(r.x), "=f"(r.y) : "l"(v)); return r;
}
__device__ __forceinline__ void fma2(u64& d, u64 a, u64 b) {
    asm("fma.rn.f32x2 %0, %1, %2, %3;" : "=l"(d) : "l"(a), "l"(b), "l"(d));
}
__device__ __forceinline__ void add2(u64& d, u64 a) {
    asm("add.rn.f32x2 %0, %1, %2;" : "=l"(d) : "l"(d), "l"(a));
}

// ---------------------------------------------------------------------------
// Kernel 0: W2 transpose (g_w2t[j][i] = W2[i][j]). 64 blocks x 256 threads.
// ---------------------------------------------------------------------------
__global__ __launch_bounds__(256) void w2t_kernel(const float* __restrict__ W2)
{
    __shared__ float t[32][33];
    const int tx = threadIdx.x & 31;
    const int ty = threadIdx.x >> 5;
    const int x0 = blockIdx.x * 32;
    const int y0 = blockIdx.y * 32;
#pragma unroll
    for (int r = 0; r < 4; r++)
        t[ty + 8 * r][tx] = W2[(size_t)(y0 + ty + 8 * r) * DH + x0 + tx];
    __syncthreads();
#pragma unroll
    for (int r = 0; r < 4; r++)
        g_w2t[(size_t)(x0 + ty + 8 * r) * DH + y0 + tx] = t[tx][ty + 8 * r];
}

// ---------------------------------------------------------------------------
// Kernel 1: features, 8 samples/block, 1024 threads, 4-way K-split, f32x2.
// Activations in smem are [k][sample] so sample PAIRS are adjacent 8 bytes.
// ---------------------------------------------------------------------------
__global__ __launch_bounds__(1024, 1) void feat_kernel(
    const float* __restrict__ x1, const float* __restrict__ x2,
    const float* __restrict__ W1, const float* __restrict__ b1,
    const float* __restrict__ W2, const float* __restrict__ b2,
    const float* __restrict__ W3)
{
    __shared__ __align__(16) float xs_t [DIN][GRP];   // 4 KB  [k][s]
    __shared__ __align__(16) float h1s_t[DH][GRP];    // 8 KB
    __shared__ __align__(16) float d2s_t[DH][GRP];    // 8 KB
    __shared__ __align__(16) u64  part2[3][4][DH];    // 24 KB [kq-1][pair][j]
    __shared__ float nacc[GRP][8];

    const int tid  = threadIdx.x;
    const int lane = tid & 31;
    const int q0   = blockIdx.x * GRP;
    const int j    = tid & 255;
    const int kq   = tid >> 8;

    if (tid < GRP * 8) nacc[tid >> 3][tid & 7] = 0.f;
    __syncthreads();

    // ---- load x (transposed to [k][s]) + x^2 norm + store x to g_feat ----
    {
        const int s = tid >> 7;           // warp-uniform
        const int i = tid & 127;
        const int q = q0 + s;
        const float* xp = (q < NB) ? (x1 + (size_t)q * DIN)
                                   : (x2 + (size_t)(q - NB) * DIN);
        const float v = xp[i];
        xs_t[i][s] = v;
        g_feat[(size_t)q * FDIM + OFF_X + i] = v;
        float ss = v * v;
#pragma unroll
        for (int o = 16; o > 0; o >>= 1) ss += __shfl_xor_sync(~0u, ss, o);
        if (lane == 0) atomicAdd(&nacc[s][NX], ss);
    }
    __syncthreads();

    float h1v[GRP];                       // kept live for d1 (kq==0 threads)

    // ================= z1 / h1 =================
    {
        u64 acc[4] = {0, 0, 0, 0};
        const int k0 = kq * (DIN / 4);    // 32 k per quarter
#pragma unroll 8
        for (int k = k0; k < k0 + DIN / 4; k++) {
            const float w = W1[k * DH + j];
            const u64 w2 = pack2(w, w);
            const ulonglong2 xa = *(const ulonglong2*)&xs_t[k][0];
            const ulonglong2 xb = *(const ulonglong2*)&xs_t[k][4];
            fma2(acc[0], w2, xa.x); fma2(acc[1], w2, xa.y);
            fma2(acc[2], w2, xb.x); fma2(acc[3], w2, xb.y);
        }
        if (kq > 0) {
#pragma unroll
            for (int p = 0; p < 4; p++) part2[kq - 1][p][j] = acc[p];
        }
        __syncthreads();
        if (kq == 0) {
            const float bj = b1[j];
#pragma unroll
            for (int p = 0; p < 4; p++) {
                add2(acc[p], part2[0][p][j]);
                add2(acc[p], part2[1][p][j]);
                add2(acc[p], part2[2][p][j]);
                const float2 z = unpk2(acc[p]);
                h1v[2 * p + 0] = fmaxf(z.x + bj, 0.f);
                h1v[2 * p + 1] = fmaxf(z.y + bj, 0.f);
            }
            float v[GRP];
#pragma unroll
            for (int s = 0; s < GRP; s++) {
                h1s_t[j][s] = h1v[s];
                g_feat[(size_t)(q0 + s) * FDIM + OFF_H1 + j] = h1v[s];
                v[s] = h1v[s] * h1v[s];
            }
#pragma unroll
            for (int s = 0; s < GRP; s++)
#pragma unroll
                for (int o = 16; o > 0; o >>= 1)
                    v[s] += __shfl_xor_sync(~0u, v[s], o);
            if (lane == 0) {
#pragma unroll
                for (int s = 0; s < GRP; s++) atomicAdd(&nacc[s][NH1], v[s]);
            }
        }
        __syncthreads();
    }

    // ================= z2 / h2 / d2 =================
    float d2v[GRP];
    {
        u64 acc[4] = {0, 0, 0, 0};
        const int k0 = kq * (DH / 4);     // 64 k per quarter
#pragma unroll 8
        for (int k = k0; k < k0 + DH / 4; k++) {
            const float w = W2[k * DH + j];
            const u64 w2 = pack2(w, w);
            const ulonglong2 ha = *(const ulonglong2*)&h1s_t[k][0];
            const ulonglong2 hb = *(const ulonglong2*)&h1s_t[k][4];
            fma2(acc[0], w2, ha.x); fma2(acc[1], w2, ha.y);
            fma2(acc[2], w2, hb.x); fma2(acc[3], w2, hb.y);
        }
        if (kq > 0) {
#pragma unroll
            for (int p = 0; p < 4; p++) part2[kq - 1][p][j] = acc[p];
        }
        __syncthreads();
        if (kq == 0) {
            const float bj  = b2[j];
            const float w3c = W3[j * DOUT + CCH];
            float h2v[GRP];
#pragma unroll
            for (int p = 0; p < 4; p++) {
                add2(acc[p], part2[0][p][j]);
                add2(acc[p], part2[1][p][j]);
                add2(acc[p], part2[2][p][j]);
                const float2 z = unpk2(acc[p]);
                const float za = z.x + bj, zb = z.y + bj;
                h2v[2 * p + 0] = fmaxf(za, 0.f);
                h2v[2 * p + 1] = fmaxf(zb, 0.f);
                d2v[2 * p + 0] = (za > 0.f) ? w3c : 0.f;
                d2v[2 * p + 1] = (zb > 0.f) ? w3c : 0.f;
            }
            float vh[GRP], vd[GRP];
#pragma unroll
            for (int s = 0; s < GRP; s++) {
                d2s_t[j][s] = d2v[s];
                float* fr = g_feat + (size_t)(q0 + s) * FDIM;
                fr[OFF_H2 + j] = h2v[s];
                fr[OFF_D2 + j] = d2v[s];
                vh[s] = h2v[s] * h2v[s];
                vd[s] = d2v[s] * d2v[s];
            }
#pragma unroll
            for (int s = 0; s < GRP; s++)
#pragma unroll
                for (int o = 16; o > 0; o >>= 1) {
                    vh[s] += __shfl_xor_sync(~0u, vh[s], o);
                    vd[s] += __shfl_xor_sync(~0u, vd[s], o);
                }
            if (lane == 0) {
#pragma unroll
                for (int s = 0; s < GRP; s++) {
                    atomicAdd(&nacc[s][NH2], vh[s]);
                    atomicAdd(&nacc[s][ND2], vd[s]);
                }
            }
        }
        __syncthreads();
    }

    // ================= d1 = relu'(z1) . (W2 d2), via W2T coalesced ========
    {
        u64 acc[4] = {0, 0, 0, 0};
        const int i  = j;
        const int k0 = kq * (DH / 4);     // 64 j-cols per quarter
#pragma unroll 8
        for (int k = k0; k < k0 + DH / 4; k++) {
            const float w = g_w2t[k * DH + i];
            const u64 w2 = pack2(w, w);
            const ulonglong2 da = *(const ulonglong2*)&d2s_t[k][0];
            const ulonglong2 db = *(const ulonglong2*)&d2s_t[k][4];
            fma2(acc[0], w2, da.x); fma2(acc[1], w2, da.y);
            fma2(acc[2], w2, db.x); fma2(acc[3], w2, db.y);
        }
        if (kq > 0) {
#pragma unroll
            for (int p = 0; p < 4; p++) part2[kq - 1][p][i] = acc[p];
        }
        __syncthreads();
        if (kq == 0) {
            float d1v[GRP];
#pragma unroll
            for (int p = 0; p < 4; p++) {
                add2(acc[p], part2[0][p][i]);
                add2(acc[p], part2[1][p][i]);
                add2(acc[p], part2[2][p][i]);
                const float2 z = unpk2(acc[p]);
                d1v[2 * p + 0] = (h1v[2 * p + 0] > 0.f) ? z.x : 0.f;
                d1v[2 * p + 1] = (h1v[2 * p + 1] > 0.f) ? z.y : 0.f;
            }
            float v[GRP];
#pragma unroll
            for (int s = 0; s < GRP; s++) {
                g_feat[(size_t)(q0 + s) * FDIM + OFF_D1 + i] = d1v[s];
                v[s] = d1v[s] * d1v[s];
            }
#pragma unroll
            for (int s = 0; s < GRP; s++)
#pragma unroll
                for (int o = 16; o > 0; o >>= 1)
                    v[s] += __shfl_xor_sync(~0u, v[s], o);
            if (lane == 0) {
#pragma unroll
                for (int s = 0; s < GRP; s++) atomicAdd(&nacc[s][ND1], v[s]);
            }
        }
        __syncthreads();
    }

    // ---- inverse norms ----
    if (tid < GRP) {
        const int s = tid;
        const float normsq = 1.f + nacc[s][NH2]
                           + (1.f + nacc[s][NH1]) * nacc[s][ND2]
                           + (1.f + nacc[s][NX])  * nacc[s][ND1];
        g_inv[q0 + s] = rsqrtf(normsq);
    }
}

// ---------------------------------------------------------------------------
// Kernel 2: split-K chunk grams, f32x2 accumulators over column pairs.
// Grid (16 tiles, 9 chunks) = 144 blocks, 256 threads, 8x8 per thread.
// ---------------------------------------------------------------------------
__global__ __launch_bounds__(256) void gram_kernel()
{
    __shared__ __align__(16) float As[2][KB][RPAD];
    __shared__ __align__(16) float Bs[2][KB][RPAD];

    const int tid   = threadIdx.x;
    const int tx    = tid & 15;
    const int ty    = tid >> 4;
    const int tile  = blockIdx.x;
    const int chunk = blockIdx.y;
    const int ti    = tile >> 2;
    const int tj    = tile & 3;

    const int arow0 = ti * 128;
    const int brow0 = NB + tj * 128;
    const int kbase = chunk * 128;

    const int e0r = tid >> 2,         e0f = tid & 3;
    const int e1r = (tid + 256) >> 2, e1f = (tid + 256) & 3;

    float4 pa0, pa1, pb0, pb1;

    auto load_stage = [&](int st) {
        const int kk = kbase + st * KB;
        pa0 = *(const float4*)(g_feat + (size_t)(arow0 + e0r) * FDIM + kk + e0f * 4);
        pa1 = *(const float4*)(g_feat + (size_t)(arow0 + e1r) * FDIM + kk + e1f * 4);
        pb0 = *(const float4*)(g_feat + (size_t)(brow0 + e0r) * FDIM + kk + e0f * 4);
        pb1 = *(const float4*)(g_feat + (size_t)(brow0 + e1r) * FDIM + kk + e1f * 4);
    };
    auto store_stage = [&](int b) {
        As[b][e0f * 4 + 0][e0r] = pa0.x; As[b][e0f * 4 + 1][e0r] = pa0.y;
        As[b][e0f * 4 + 2][e0r] = pa0.z; As[b][e0f * 4 + 3][e0r] = pa0.w;
        As[b][e1f * 4 + 0][e1r] = pa1.x; As[b][e1f * 4 + 1][e1r] = pa1.y;
        As[b][e1f * 4 + 2][e1r] = pa1.z; As[b][e1f * 4 + 3][e1r] = pa1.w;
        Bs[b][e0f * 4 + 0][e0r] = pb0.x; Bs[b][e0f * 4 + 1][e0r] = pb0.y;
        Bs[b][e0f * 4 + 2][e0r] = pb0.z; Bs[b][e0f * 4 + 3][e0r] = pb0.w;
        Bs[b][e1f * 4 + 0][e1r] = pb1.x; Bs[b][e1f * 4 + 1][e1r] = pb1.y;
        Bs[b][e1f * 4 + 2][e1r] = pb1.z; Bs[b][e1f * 4 + 3][e1r] = pb1.w;
    };

    u64 acc2[8][4];
#pragma unroll
    for (int i = 0; i < 8; i++)
#pragma unroll
        for (int p = 0; p < 4; p++) acc2[i][p] = 0ull;

    load_stage(0);
    store_stage(0);
    __syncthreads();

    const int NSTAGE = 128 / KB;
#pragma unroll 1
    for (int st = 0; st < NSTAGE; st++) {
        if (st < NSTAGE - 1) load_stage(st + 1);
        const int b = st & 1;
#pragma unroll
        for (int k = 0; k < KB; k++) {
            const float4 a0 = *(const float4*)&As[b][k][ty * 4];
            const float4 a1 = *(const float4*)&As[b][k][64 + ty * 4];
            const ulonglong2 b0 = *(const ulonglong2*)&Bs[b][k][tx * 4];
            const ulonglong2 b1 = *(const ulonglong2*)&Bs[b][k][64 + tx * 4];
            const u64 bv[4] = {b0.x, b0.y, b1.x, b1.y};
            const u64 ad[8] = {pack2(a0.x, a0.x), pack2(a0.y, a0.y),
                               pack2(a0.z, a0.z), pack2(a0.w, a0.w),
                               pack2(a1.x, a1.x), pack2(a1.y, a1.y),
                               pack2(a1.z, a1.z), pack2(a1.w, a1.w)};
#pragma unroll
            for (int i = 0; i < 8; i++)
#pragma unroll
                for (int p = 0; p < 4; p++)
                    fma2(acc2[i][p], ad[i], bv[p]);
        }
        if (st < NSTAGE - 1) store_stage(b ^ 1);
        __syncthreads();
    }

    // Epilogue: each acc2 pair is two adjacent output columns — store as u64x2.
    float* scr = g_scr + (size_t)chunk * NB * NB;
#pragma unroll
    for (int ri = 0; ri < 2; ri++) {
#pragma unroll
        for (int r = 0; r < 4; r++) {
            const int i = ri * 4 + r;
            const int m = ti * 128 + ri * 64 + ty * 4 + r;
            float* rp = scr + (size_t)m * NB + tj * 128;
            ulonglong2 v0, v1;
            v0.x = acc2[i][0]; v0.y = acc2[i][1];
            v1.x = acc2[i][2]; v1.y = acc2[i][3];
            *(ulonglong2*)(rp + tx * 4)      = v0;
            *(ulonglong2*)(rp + 64 + tx * 4) = v1;
        }
    }
}

// ---------------------------------------------------------------------------
// Kernel 3: combine chunk grams + normalize.
// chunks: 0,1 -> h1 | 2,3 -> d2 | 4 -> x | 5,6 -> d1 | 7,8 -> h2
// ---------------------------------------------------------------------------
__global__ __launch_bounds__(256) void combine_kernel(float* __restrict__ out)
{
    const int gid = blockIdx.x * 256 + threadIdx.x;
    const int row = gid >> 7;
    const int c4  = gid & 127;

    const size_t off = (size_t)row * NB;
    float4 g[9];
#pragma unroll
    for (int c = 0; c < 9; c++)
        g[c] = ((const float4*)(g_scr + (size_t)c * NB * NB + off))[c4];

    const float  ia = g_inv[row];
    const float4 ib = *(const float4*)&g_inv[NB + c4 * 4];

    float4 r;
    r.x = (1.f + g[7].x + g[8].x + (1.f + g[0].x + g[1].x) * (g[2].x + g[3].x)
           + (1.f + g[4].x) * (g[5].x + g[6].x)) * ia * ib.x;
    r.y = (1.f + g[7].y + g[8].y + (1.f + g[0].y + g[1].y) * (g[2].y + g[3].y)
           + (1.f + g[4].y) * (g[5].y + g[6].y)) * ia * ib.y;
    r.z = (1.f + g[7].z + g[8].z + (1.f + g[0].z + g[1].z) * (g[2].z + g[3].z)
           + (1.f + g[4].z) * (g[5].z + g[6].z)) * ia * ib.z;
    r.w = (1.f + g[7].w + g[8].w + (1.f + g[0].w + g[1].w) * (g[2].w + g[3].w)
           + (1.f + g[4].w) * (g[5].w + g[6].w)) * ia * ib.w;

    ((float4*)(out + off))[c4] = r;
}

// ---------------------------------------------------------------------------
// inputs: x1, x2, W1, b1, W2, b2, W3, b3 ; output [512,512] float32
// ---------------------------------------------------------------------------
extern "C" void kernel_launch(void* const* d_in, const int* in_sizes, int n_in,
                              void* d_out, int out_size)
{
    const float* x1 = (const float*)d_in[0];
    const float* x2 = (const float*)d_in[1];
    const float* W1 = (const float*)d_in[2];
    const float* b1 = (const float*)d_in[3];
    const float* W2 = (const float*)d_in[4];
    const float* b2 = (const float*)d_in[5];
    const float* W3 = (const float*)d_in[6];
    float* out = (float*)d_out;

    w2t_kernel<<<dim3(8, 8), 256>>>(W2);
    feat_kernel<<<(2 * NB) / GRP, 1024>>>(x1, x2, W1, b1, W2, b2, W3);
    gram_kernel<<<dim3(16, 9), 256>>>();
    combine_kernel<<<256, 256>>>(out);
}

// round 6
// speedup vs baseline: 2.8072x; 1.0120x over previous
#include <cuda_runtime.h>

typedef unsigned long long u64;

// Problem constants
#define NB     512
#define DIN    128
#define DH     256
#define DOUT   10
#define CCH    0

// Feature layout per sample: [h1(256) | d2(256) | x(128) | d1(256) | h2(256)]
#define OFF_H1 0
#define OFF_D2 256
#define OFF_X  512
#define OFF_D1 640
#define OFF_H2 896
#define FDIM   1152

#define GRP    8      // samples per feat block
#define KB     16     // gram k sub-chunk (double buffered)
#define RPAD   132    // padded smem row (floats)

// norm indices
#define NX  0
#define NH1 1
#define ND2 2
#define ND1 3
#define NH2 4

// Scratch
__device__ __align__(16) float g_feat[2 * NB * FDIM];   // 4.7 MB
__device__ float g_inv[2 * NB];
__device__ __align__(16) float g_scr[9 * NB * NB];      // 9.4 MB chunk grams
__device__ __align__(16) float g_w2t[DH * DH];          // W2 transposed

// ---- packed f32x2 helpers (Blackwell) ----
__device__ __forceinline__ u64 pack2(float lo, float hi) {
    u64 r; asm("mov.b64 %0, {%1, %2};" : "=l"(r) : "f"(lo), "f"(hi)); return r;
}
__device__ __forceinline__ float2 unpk2(u64 v) {
    float2 r; asm("mov.b64 {%0, %1}, %2;" : "=f"(r.x), "=f"(r.y) : "l"(v)); return r;
}
__device__ __forceinline__ void fma2(u64& d, u64 a, u64 b) {
    asm("fma.rn.f32x2 %0, %1, %2, %3;" : "=l"(d) : "l"(a), "l"(b), "l"(d));
}
__device__ __forceinline__ void add2(u64& d, u64 a) {
    asm("add.rn.f32x2 %0, %1, %2;" : "=l"(d) : "l"(d), "l"(a));
}

// ---------------------------------------------------------------------------
// Kernel 0: W2 transpose (g_w2t[j][i] = W2[i][j]). 64 blocks x 256 threads.
// ---------------------------------------------------------------------------
__global__ __launch_bounds__(256) void w2t_kernel(const float* __restrict__ W2)
{
    __shared__ float t[32][33];
    const int tx = threadIdx.x & 31;
    const int ty = threadIdx.x >> 5;
    const int x0 = blockIdx.x * 32;
    const int y0 = blockIdx.y * 32;
#pragma unroll
    for (int r = 0; r < 4; r++)
        t[ty + 8 * r][tx] = W2[(size_t)(y0 + ty + 8 * r) * DH + x0 + tx];
    __syncthreads();
#pragma unroll
    for (int r = 0; r < 4; r++)
        g_w2t[(size_t)(x0 + ty + 8 * r) * DH + y0 + tx] = t[tx][ty + 8 * r];
}

// ---------------------------------------------------------------------------
// Kernel 1: features, 8 samples/block, 512 threads, 2-way K-split, f32x2.
// 128 blocks. Threads: col j = tid&255, K-half kq = tid>>8 (0 or 1).
// 512 threads -> 128 regs/thread available: no register spills.
// ---------------------------------------------------------------------------
__global__ __launch_bounds__(512, 1) void feat_kernel(
    const float* __restrict__ x1, const float* __restrict__ x2,
    const float* __restrict__ W1, const float* __restrict__ b1,
    const float* __restrict__ W2, const float* __restrict__ b2,
    const float* __restrict__ W3)
{
    __shared__ __align__(16) float xs_t [DIN][GRP];   // 4 KB  [k][s]
    __shared__ __align__(16) float h1s_t[DH][GRP];    // 8 KB
    __shared__ __align__(16) float d2s_t[DH][GRP];    // 8 KB
    __shared__ __align__(16) u64  part2[4][DH];       // 8 KB  [pair][j] (kq=1)
    __shared__ float nacc[GRP][8];

    const int tid  = threadIdx.x;
    const int lane = tid & 31;
    const int q0   = blockIdx.x * GRP;
    const int j    = tid & 255;
    const int kq   = tid >> 8;            // 0 or 1

    if (tid < GRP * 8) nacc[tid >> 3][tid & 7] = 0.f;
    __syncthreads();

    // ---- load x (transposed to [k][s]) + x^2 norm + store x to g_feat ----
    {
        const int s = tid >> 6;           // 0..7, warp-uniform (64 thr/sample)
        const int i0 = (tid & 63) * 2;    // 2 elems per thread
        const int q = q0 + s;
        const float* xp = (q < NB) ? (x1 + (size_t)q * DIN)
                                   : (x2 + (size_t)(q - NB) * DIN);
        const float v0 = xp[i0], v1 = xp[i0 + 1];
        xs_t[i0][s] = v0; xs_t[i0 + 1][s] = v1;
        g_feat[(size_t)q * FDIM + OFF_X + i0]     = v0;
        g_feat[(size_t)q * FDIM + OFF_X + i0 + 1] = v1;
        float ss = v0 * v0 + v1 * v1;
#pragma unroll
        for (int o = 16; o > 0; o >>= 1) ss += __shfl_xor_sync(~0u, ss, o);
        if (lane == 0) atomicAdd(&nacc[s][NX], ss);
    }
    __syncthreads();

    float h1v[GRP];                       // live for d1 (kq==0 threads)

    // ================= z1 / h1 =================
    {
        u64 acc[4] = {0, 0, 0, 0};
        const int k0 = kq * (DIN / 2);    // 64 k per half
#pragma unroll 8
        for (int k = k0; k < k0 + DIN / 2; k++) {
            const float w = W1[k * DH + j];
            const u64 w2 = pack2(w, w);
            const ulonglong2 xa = *(const ulonglong2*)&xs_t[k][0];
            const ulonglong2 xb = *(const ulonglong2*)&xs_t[k][4];
            fma2(acc[0], w2, xa.x); fma2(acc[1], w2, xa.y);
            fma2(acc[2], w2, xb.x); fma2(acc[3], w2, xb.y);
        }
        if (kq == 1) {
#pragma unroll
            for (int p = 0; p < 4; p++) part2[p][j] = acc[p];
        }
        __syncthreads();
        if (kq == 0) {
            const float bj = b1[j];
#pragma unroll
            for (int p = 0; p < 4; p++) {
                add2(acc[p], part2[p][j]);
                const float2 z = unpk2(acc[p]);
                h1v[2 * p + 0] = fmaxf(z.x + bj, 0.f);
                h1v[2 * p + 1] = fmaxf(z.y + bj, 0.f);
            }
            float v[GRP];
#pragma unroll
            for (int s = 0; s < GRP; s++) {
                h1s_t[j][s] = h1v[s];
                g_feat[(size_t)(q0 + s) * FDIM + OFF_H1 + j] = h1v[s];
                v[s] = h1v[s] * h1v[s];
            }
#pragma unroll
            for (int s = 0; s < GRP; s++)
#pragma unroll
                for (int o = 16; o > 0; o >>= 1)
                    v[s] += __shfl_xor_sync(~0u, v[s], o);
            if (lane == 0) {
#pragma unroll
                for (int s = 0; s < GRP; s++) atomicAdd(&nacc[s][NH1], v[s]);
            }
        }
        __syncthreads();
    }

    // ================= z2 / h2 / d2 =================
    {
        u64 acc[4] = {0, 0, 0, 0};
        const int k0 = kq * (DH / 2);     // 128 k per half
#pragma unroll 8
        for (int k = k0; k < k0 + DH / 2; k++) {
            const float w = W2[k * DH + j];
            const u64 w2 = pack2(w, w);
            const ulonglong2 ha = *(const ulonglong2*)&h1s_t[k][0];
            const ulonglong2 hb = *(const ulonglong2*)&h1s_t[k][4];
            fma2(acc[0], w2, ha.x); fma2(acc[1], w2, ha.y);
            fma2(acc[2], w2, hb.x); fma2(acc[3], w2, hb.y);
        }
        if (kq == 1) {
#pragma unroll
            for (int p = 0; p < 4; p++) part2[p][j] = acc[p];
        }
        __syncthreads();
        if (kq == 0) {
            const float bj  = b2[j];
            const float w3c = W3[j * DOUT + CCH];
            float h2v[GRP], d2v[GRP];
#pragma unroll
            for (int p = 0; p < 4; p++) {
                add2(acc[p], part2[p][j]);
                const float2 z = unpk2(acc[p]);
                const float za = z.x + bj, zb = z.y + bj;
                h2v[2 * p + 0] = fmaxf(za, 0.f);
                h2v[2 * p + 1] = fmaxf(zb, 0.f);
                d2v[2 * p + 0] = (za > 0.f) ? w3c : 0.f;
                d2v[2 * p + 1] = (zb > 0.f) ? w3c : 0.f;
            }
            float vh[GRP], vd[GRP];
#pragma unroll
            for (int s = 0; s < GRP; s++) {
                d2s_t[j][s] = d2v[s];
                float* fr = g_feat + (size_t)(q0 + s) * FDIM;
                fr[OFF_H2 + j] = h2v[s];
                fr[OFF_D2 + j] = d2v[s];
                vh[s] = h2v[s] * h2v[s];
                vd[s] = d2v[s] * d2v[s];
            }
#pragma unroll
            for (int s = 0; s < GRP; s++)
#pragma unroll
                for (int o = 16; o > 0; o >>= 1) {
                    vh[s] += __shfl_xor_sync(~0u, vh[s], o);
                    vd[s] += __shfl_xor_sync(~0u, vd[s], o);
                }
            if (lane == 0) {
#pragma unroll
                for (int s = 0; s < GRP; s++) {
                    atomicAdd(&nacc[s][NH2], vh[s]);
                    atomicAdd(&nacc[s][ND2], vd[s]);
                }
            }
        }
        __syncthreads();
    }

    // ================= d1 = relu'(z1) . (W2 d2), via W2T coalesced ========
    {
        u64 acc[4] = {0, 0, 0, 0};
        const int i  = j;
        const int k0 = kq * (DH / 2);     // 128 j-cols per half
#pragma unroll 8
        for (int k = k0; k < k0 + DH / 2; k++) {
            const float w = g_w2t[k * DH + i];
            const u64 w2 = pack2(w, w);
            const ulonglong2 da = *(const ulonglong2*)&d2s_t[k][0];
            const ulonglong2 db = *(const ulonglong2*)&d2s_t[k][4];
            fma2(acc[0], w2, da.x); fma2(acc[1], w2, da.y);
            fma2(acc[2], w2, db.x); fma2(acc[3], w2, db.y);
        }
        if (kq == 1) {
#pragma unroll
            for (int p = 0; p < 4; p++) part2[p][i] = acc[p];
        }
        __syncthreads();
        if (kq == 0) {
            float d1v[GRP];
#pragma unroll
            for (int p = 0; p < 4; p++) {
                add2(acc[p], part2[p][i]);
                const float2 z = unpk2(acc[p]);
                d1v[2 * p + 0] = (h1v[2 * p + 0] > 0.f) ? z.x : 0.f;
                d1v[2 * p + 1] = (h1v[2 * p + 1] > 0.f) ? z.y : 0.f;
            }
            float v[GRP];
#pragma unroll
            for (int s = 0; s < GRP; s++) {
                g_feat[(size_t)(q0 + s) * FDIM + OFF_D1 + i] = d1v[s];
                v[s] = d1v[s] * d1v[s];
            }
#pragma unroll
            for (int s = 0; s < GRP; s++)
#pragma unroll
                for (int o = 16; o > 0; o >>= 1)
                    v[s] += __shfl_xor_sync(~0u, v[s], o);
            if (lane == 0) {
#pragma unroll
                for (int s = 0; s < GRP; s++) atomicAdd(&nacc[s][ND1], v[s]);
            }
        }
        __syncthreads();
    }

    // ---- inverse norms ----
    if (tid < GRP) {
        const int s = tid;
        const float normsq = 1.f + nacc[s][NH2]
                           + (1.f + nacc[s][NH1]) * nacc[s][ND2]
                           + (1.f + nacc[s][NX])  * nacc[s][ND1];
        g_inv[q0 + s] = rsqrtf(normsq);
    }
}

// ---------------------------------------------------------------------------
// Kernel 2: split-K chunk grams, f32x2 accumulators over column pairs.
// Grid (16 tiles, 9 chunks) = 144 blocks, 256 threads, 8x8 per thread.
// ---------------------------------------------------------------------------
__global__ __launch_bounds__(256) void gram_kernel()
{
    __shared__ __align__(16) float As[2][KB][RPAD];
    __shared__ __align__(16) float Bs[2][KB][RPAD];

    const int tid   = threadIdx.x;
    const int tx    = tid & 15;
    const int ty    = tid >> 4;
    const int tile  = blockIdx.x;
    const int chunk = blockIdx.y;
    const int ti    = tile >> 2;
    const int tj    = tile & 3;

    const int arow0 = ti * 128;
    const int brow0 = NB + tj * 128;
    const int kbase = chunk * 128;

    const int e0r = tid >> 2,         e0f = tid & 3;
    const int e1r = (tid + 256) >> 2, e1f = (tid + 256) & 3;

    float4 pa0, pa1, pb0, pb1;

    auto load_stage = [&](int st) {
        const int kk = kbase + st * KB;
        pa0 = *(const float4*)(g_feat + (size_t)(arow0 + e0r) * FDIM + kk + e0f * 4);
        pa1 = *(const float4*)(g_feat + (size_t)(arow0 + e1r) * FDIM + kk + e1f * 4);
        pb0 = *(const float4*)(g_feat + (size_t)(brow0 + e0r) * FDIM + kk + e0f * 4);
        pb1 = *(const float4*)(g_feat + (size_t)(brow0 + e1r) * FDIM + kk + e1f * 4);
    };
    auto store_stage = [&](int b) {
        As[b][e0f * 4 + 0][e0r] = pa0.x; As[b][e0f * 4 + 1][e0r] = pa0.y;
        As[b][e0f * 4 + 2][e0r] = pa0.z; As[b][e0f * 4 + 3][e0r] = pa0.w;
        As[b][e1f * 4 + 0][e1r] = pa1.x; As[b][e1f * 4 + 1][e1r] = pa1.y;
        As[b][e1f * 4 + 2][e1r] = pa1.z; As[b][e1f * 4 + 3][e1r] = pa1.w;
        Bs[b][e0f * 4 + 0][e0r] = pb0.x; Bs[b][e0f * 4 + 1][e0r] = pb0.y;
        Bs[b][e0f * 4 + 2][e0r] = pb0.z; Bs[b][e0f * 4 + 3][e0r] = pb0.w;
        Bs[b][e1f * 4 + 0][e1r] = pb1.x; Bs[b][e1f * 4 + 1][e1r] = pb1.y;
        Bs[b][e1f * 4 + 2][e1r] = pb1.z; Bs[b][e1f * 4 + 3][e1r] = pb1.w;
    };

    u64 acc2[8][4];
#pragma unroll
    for (int i = 0; i < 8; i++)
#pragma unroll
        for (int p = 0; p < 4; p++) acc2[i][p] = 0ull;

    load_stage(0);
    store_stage(0);
    __syncthreads();

    const int NSTAGE = 128 / KB;
#pragma unroll 1
    for (int st = 0; st < NSTAGE; st++) {
        if (st < NSTAGE - 1) load_stage(st + 1);
        const int b = st & 1;
#pragma unroll
        for (int k = 0; k < KB; k++) {
            const float4 a0 = *(const float4*)&As[b][k][ty * 4];
            const float4 a1 = *(const float4*)&As[b][k][64 + ty * 4];
            const ulonglong2 b0 = *(const ulonglong2*)&Bs[b][k][tx * 4];
            const ulonglong2 b1 = *(const ulonglong2*)&Bs[b][k][64 + tx * 4];
            const u64 bv[4] = {b0.x, b0.y, b1.x, b1.y};
            const u64 ad[8] = {pack2(a0.x, a0.x), pack2(a0.y, a0.y),
                               pack2(a0.z, a0.z), pack2(a0.w, a0.w),
                               pack2(a1.x, a1.x), pack2(a1.y, a1.y),
                               pack2(a1.z, a1.z), pack2(a1.w, a1.w)};
#pragma unroll
            for (int i = 0; i < 8; i++)
#pragma unroll
                for (int p = 0; p < 4; p++)
                    fma2(acc2[i][p], ad[i], bv[p]);
        }
        if (st < NSTAGE - 1) store_stage(b ^ 1);
        __syncthreads();
    }

    float* scr = g_scr + (size_t)chunk * NB * NB;
#pragma unroll
    for (int ri = 0; ri < 2; ri++) {
#pragma unroll
        for (int r = 0; r < 4; r++) {
            const int i = ri * 4 + r;
            const int m = ti * 128 + ri * 64 + ty * 4 + r;
            float* rp = scr + (size_t)m * NB + tj * 128;
            ulonglong2 v0, v1;
            v0.x = acc2[i][0]; v0.y = acc2[i][1];
            v1.x = acc2[i][2]; v1.y = acc2[i][3];
            *(ulonglong2*)(rp + tx * 4)      = v0;
            *(ulonglong2*)(rp + 64 + tx * 4) = v1;
        }
    }
}

// ---------------------------------------------------------------------------
// Kernel 3: combine chunk grams + normalize.
// chunks: 0,1 -> h1 | 2,3 -> d2 | 4 -> x | 5,6 -> d1 | 7,8 -> h2
// ---------------------------------------------------------------------------
__global__ __launch_bounds__(256) void combine_kernel(float* __restrict__ out)
{
    const int gid = blockIdx.x * 256 + threadIdx.x;
    const int row = gid >> 7;
    const int c4  = gid & 127;

    const size_t off = (size_t)row * NB;
    float4 g[9];
#pragma unroll
    for (int c = 0; c < 9; c++)
        g[c] = ((const float4*)(g_scr + (size_t)c * NB * NB + off))[c4];

    const float  ia = g_inv[row];
    const float4 ib = *(const float4*)&g_inv[NB + c4 * 4];

    float4 r;
    r.x = (1.f + g[7].x + g[8].x + (1.f + g[0].x + g[1].x) * (g[2].x + g[3].x)
           + (1.f + g[4].x) * (g[5].x + g[6].x)) * ia * ib.x;
    r.y = (1.f + g[7].y + g[8].y + (1.f + g[0].y + g[1].y) * (g[2].y + g[3].y)
           + (1.f + g[4].y) * (g[5].y + g[6].y)) * ia * ib.y;
    r.z = (1.f + g[7].z + g[8].z + (1.f + g[0].z + g[1].z) * (g[2].z + g[3].z)
           + (1.f + g[4].z) * (g[5].z + g[6].z)) * ia * ib.z;
    r.w = (1.f + g[7].w + g[8].w + (1.f + g[0].w + g[1].w) * (g[2].w + g[3].w)
           + (1.f + g[4].w) * (g[5].w + g[6].w)) * ia * ib.w;

    ((float4*)(out + off))[c4] = r;
}

// ---------------------------------------------------------------------------
// inputs: x1, x2, W1, b1, W2, b2, W3, b3 ; output [512,512] float32
// ---------------------------------------------------------------------------
extern "C" void kernel_launch(void* const* d_in, const int* in_sizes, int n_in,
                              void* d_out, int out_size)
{
    const float* x1 = (const float*)d_in[0];
    const float* x2 = (const float*)d_in[1];
    const float* W1 = (const float*)d_in[2];
    const float* b1 = (const float*)d_in[3];
    const float* W2 = (const float*)d_in[4];
    const float* b2 = (const float*)d_in[5];
    const float* W3 = (const float*)d_in[6];
    float* out = (float*)d_out;

    w2t_kernel<<<dim3(8, 8), 256>>>(W2);
    feat_kernel<<<(2 * NB) / GRP, 512>>>(x1, x2, W1, b1, W2, b2, W3);
    gram_kernel<<<dim3(16, 9), 256>>>();
    combine_kernel<<<256, 256>>>(out);
}